// round 4
// baseline (speedup 1.0000x reference)
#include <cuda_runtime.h>
#include <math.h>

#define NN 100000
#define NE 3200000
#define F0 35
#define F0P 36
#define F1 64

// ---- scratch (device globals; no dynamic allocation allowed) ----
__device__ float g_deg[NN];                         // deg, then dinv in-place
__device__ __align__(16) float g_xpad[NN * F0P];    // x padded to 36 cols
__device__ __align__(16) float g_aggx[NN * F0P];    // layer-1 aggregated features
__device__ float g_norm[NE];
__device__ __align__(16) float g_h1[NN * F1];       // relu(aggx@W1+b1)
__device__ __align__(8)  float g_h2[NN * 2];        // h1@W2
__device__ __align__(8)  float g_agg2[NN * 2];      // layer-2 aggregation

// K0: pad x into g_xpad, init deg=1 (self-loop weight)
__global__ void k_init(const float* __restrict__ x) {
    int idx = blockIdx.x * blockDim.x + threadIdx.x;
    if (idx >= NN * F0P) return;
    int n = idx / F0P;
    int f = idx - n * F0P;
    g_xpad[idx] = (f < F0) ? x[n * F0 + f] : 0.0f;
    if (f == 0) g_deg[n] = 1.0f;
}

// K1: weighted in-degree (edge_index arrives as int32 from the harness:
// ei[0..NE) = src row, ei[NE..2NE) = dst row)
__global__ void k_edge_pre(const int* __restrict__ ei, const float* __restrict__ ew) {
    int e = blockIdx.x * blockDim.x + threadIdx.x;
    if (e >= NE) return;
    int d = ei[NE + e];
    atomicAdd(&g_deg[d], ew[e]);
}

// K2: deg -> dinv
__global__ void k_dinv() {
    int n = blockIdx.x * blockDim.x + threadIdx.x;
    if (n >= NN) return;
    float d = g_deg[n];
    g_deg[n] = (d > 0.0f) ? rsqrtf(d) : 0.0f;
}

// K3: per-edge norm = dinv[src]*w*dinv[dst]
__global__ void k_norm(const int* __restrict__ ei, const float* __restrict__ ew) {
    int e = blockIdx.x * blockDim.x + threadIdx.x;
    if (e >= NE) return;
    int s = ei[e];
    int d = ei[NE + e];
    g_norm[e] = g_deg[s] * ew[e] * g_deg[d];
}

// K4: init aggx with self-loop contribution: dinv^2 * x
__global__ void k_self1() {
    int idx = blockIdx.x * blockDim.x + threadIdx.x;
    if (idx >= NN * F0P) return;
    int n = idx / F0P;
    float di = g_deg[n];
    g_aggx[idx] = di * di * g_xpad[idx];
}

// K5: layer-1 edge aggregation. one thread per (edge, float4 chunk of 9)
__global__ void k_agg1(const int* __restrict__ ei) {
    long long t = (long long)blockIdx.x * blockDim.x + threadIdx.x;
    if (t >= (long long)NE * 9) return;
    int e = (int)(t / 9);
    int q = (int)(t - (long long)e * 9);
    int s = ei[e];
    int d = ei[NE + e];
    float w = g_norm[e];
    float4 v = ((const float4*)g_xpad)[s * 9 + q];
    float* dst = g_aggx + d * F0P + q * 4;
    atomicAdd(dst + 0, w * v.x);
    atomicAdd(dst + 1, w * v.y);
    atomicAdd(dst + 2, w * v.z);
    atomicAdd(dst + 3, w * v.w);
}

// K6: h1 = relu(aggx @ W1 + b1). 256 threads = 4 nodes x 64 outputs
__global__ void k_gemm1(const float* __restrict__ W1, const float* __restrict__ b1) {
    __shared__ float sW[F0 * F1];
    __shared__ float sb[F1];
    __shared__ float sx[4 * F0P];
    int tid = threadIdx.x;
    for (int i = tid; i < F0 * F1; i += 256) sW[i] = W1[i];
    if (tid < F1) sb[tid] = b1[tid];
    int base = blockIdx.x * 4;
    for (int i = tid; i < 4 * F0P; i += 256) {
        int n = base + i / F0P;
        sx[i] = (n < NN) ? g_aggx[n * F0P + (i % F0P)] : 0.0f;
    }
    __syncthreads();
    int o  = tid & 63;
    int ni = tid >> 6;
    int n = base + ni;
    if (n >= NN) return;
    float acc = sb[o];
#pragma unroll
    for (int f = 0; f < F0; f++)
        acc += sx[ni * F0P + f] * sW[f * F1 + o];
    g_h1[n * F1 + o] = fmaxf(acc, 0.0f);
}

// K7: h2 = h1 @ W2, plus self-loop init of agg2 (dinv^2 * h2)
__global__ void k_h2(const float* __restrict__ W2) {
    __shared__ float sW[F1 * 2];
    if (threadIdx.x < F1 * 2) sW[threadIdx.x] = W2[threadIdx.x];
    __syncthreads();
    int n = blockIdx.x * blockDim.x + threadIdx.x;
    if (n >= NN) return;
    const float4* hv = (const float4*)(g_h1 + n * F1);
    float a0 = 0.0f, a1 = 0.0f;
#pragma unroll
    for (int i = 0; i < 16; i++) {
        float4 v = hv[i];
        int k = i * 4;
        a0 += v.x * sW[(k + 0) * 2 + 0] + v.y * sW[(k + 1) * 2 + 0]
            + v.z * sW[(k + 2) * 2 + 0] + v.w * sW[(k + 3) * 2 + 0];
        a1 += v.x * sW[(k + 0) * 2 + 1] + v.y * sW[(k + 1) * 2 + 1]
            + v.z * sW[(k + 2) * 2 + 1] + v.w * sW[(k + 3) * 2 + 1];
    }
    float di = g_deg[n];
    ((float2*)g_h2)[n]   = make_float2(a0, a1);
    ((float2*)g_agg2)[n] = make_float2(di * di * a0, di * di * a1);
}

// K8: layer-2 edge aggregation. one thread per edge, 2 scalar atomics
__global__ void k_agg2(const int* __restrict__ ei) {
    int e = blockIdx.x * blockDim.x + threadIdx.x;
    if (e >= NE) return;
    int s = ei[e];
    int d = ei[NE + e];
    float w = g_norm[e];
    float2 h = ((const float2*)g_h2)[s];
    atomicAdd(&g_agg2[d * 2 + 0], w * h.x);
    atomicAdd(&g_agg2[d * 2 + 1], w * h.y);
}

// K9: +b2, log_softmax over 2 classes, write output
__global__ void k_out(const float* __restrict__ b2, float* __restrict__ out) {
    int n = blockIdx.x * blockDim.x + threadIdx.x;
    if (n >= NN) return;
    float2 a = ((const float2*)g_agg2)[n];
    a.x += b2[0];
    a.y += b2[1];
    float m = fmaxf(a.x, a.y);
    float lse = m + logf(expf(a.x - m) + expf(a.y - m));
    ((float2*)out)[n] = make_float2(a.x - lse, a.y - lse);
}

extern "C" void kernel_launch(void* const* d_in, const int* in_sizes, int n_in,
                              void* d_out, int out_size) {
    const float* x = nullptr;
    const int* ei = nullptr;
    const float* ew = nullptr;
    const float *W1 = nullptr, *b1 = nullptr, *W2 = nullptr, *b2 = nullptr;
    for (int i = 0; i < n_in; i++) {
        switch (in_sizes[i]) {
            case NN * F0:  x  = (const float*)d_in[i]; break;
            case 2 * NE:   ei = (const int*)d_in[i]; break;
            case NE:       ew = (const float*)d_in[i]; break;
            case F0 * F1:  W1 = (const float*)d_in[i]; break;
            case F1:       b1 = (const float*)d_in[i]; break;
            case F1 * 2:   W2 = (const float*)d_in[i]; break;
            case 2:        b2 = (const float*)d_in[i]; break;
            default: break;
        }
    }
    float* out = (float*)d_out;

    const int B = 256;
    k_init<<<(NN * F0P + B - 1) / B, B>>>(x);
    k_edge_pre<<<(NE + B - 1) / B, B>>>(ei, ew);
    k_dinv<<<(NN + B - 1) / B, B>>>();
    k_norm<<<(NE + B - 1) / B, B>>>(ei, ew);
    k_self1<<<(NN * F0P + B - 1) / B, B>>>();
    k_agg1<<<(int)(((long long)NE * 9 + B - 1) / B), B>>>(ei);
    k_gemm1<<<(NN + 3) / 4, 256>>>(W1, b1);
    k_h2<<<(NN + B - 1) / B, B>>>(W2);
    k_agg2<<<(NE + B - 1) / B, B>>>(ei);
    k_out<<<(NN + B - 1) / B, B>>>(b2, out);
}

// round 5
// speedup vs baseline: 1.0769x; 1.0769x over previous
#include <cuda_runtime.h>
#include <math.h>

#define NN 100000
#define NE 3200000
#define F0 35
#define F0P 36
#define F1 64

// ---- scratch (device globals) ----
__device__ float g_deg[NN];                        // weighted deg, then dinv
__device__ int   g_cnt[NN];                        // in-degree count
__device__ int   g_off[NN + 1];                    // CSR offsets
__device__ int   g_woff[NN];                       // working offsets for scatter
__device__ int   g_csrc[NE];                       // CSR: src per edge (dst-sorted)
__device__ float g_cnorm[NE];                      // CSR: norm per edge
__device__ __align__(16) float g_xpad[NN * F0P];   // x padded to 36 cols
__device__ __align__(16) float g_aggx[NN * F0P];   // layer-1 aggregate
__device__ __align__(16) float g_h1[NN * F1];      // relu(aggx@W1+b1)
__device__ __align__(8)  float g_h2[NN * 2];       // h1@W2
__device__ __align__(8)  float g_agg2[NN * 2];     // layer-2 aggregate

// K0: pad x, init deg=1 (self-loop weight), cnt=0
__global__ void k_init(const float* __restrict__ x) {
    int idx = blockIdx.x * blockDim.x + threadIdx.x;
    if (idx >= NN * F0P) return;
    int n = idx / F0P;
    int f = idx - n * F0P;
    g_xpad[idx] = (f < F0) ? x[n * F0 + f] : 0.0f;
    if (f == 0) { g_deg[n] = 1.0f; g_cnt[n] = 0; }
}

// K1: weighted in-degree + count histogram
__global__ void k_hist(const int* __restrict__ ei, const float* __restrict__ ew) {
    int e = blockIdx.x * blockDim.x + threadIdx.x;
    if (e >= NE) return;
    int d = ei[NE + e];
    atomicAdd(&g_deg[d], ew[e]);
    atomicAdd(&g_cnt[d], 1);
}

// K2: deg -> dinv
__global__ void k_dinv() {
    int n = blockIdx.x * blockDim.x + threadIdx.x;
    if (n >= NN) return;
    float d = g_deg[n];
    g_deg[n] = (d > 0.0f) ? rsqrtf(d) : 0.0f;
}

// K3: single-block exclusive scan of g_cnt -> g_off / g_woff
__global__ void k_scan() {
    __shared__ int part[1024];
    const int tid = threadIdx.x;
    const int CH = (NN + 1023) / 1024;   // 98
    int base = tid * CH;
    int sum = 0;
    for (int i = 0; i < CH; i++) {
        int n = base + i;
        if (n < NN) sum += g_cnt[n];
    }
    part[tid] = sum;
    __syncthreads();
    // Hillis-Steele inclusive scan
    for (int o = 1; o < 1024; o <<= 1) {
        int t = (tid >= o) ? part[tid - o] : 0;
        __syncthreads();
        part[tid] += t;
        __syncthreads();
    }
    int run = part[tid] - sum;   // exclusive prefix for this chunk
    for (int i = 0; i < CH; i++) {
        int n = base + i;
        if (n < NN) {
            g_off[n] = run;
            g_woff[n] = run;
            run += g_cnt[n];
        }
    }
    if (tid == 1023) g_off[NN] = part[1023];
}

// K4: scatter edges into CSR (dst-sorted), computing norm on the fly
__global__ void k_scatter(const int* __restrict__ ei, const float* __restrict__ ew) {
    int e = blockIdx.x * blockDim.x + threadIdx.x;
    if (e >= NE) return;
    int s = ei[e];
    int d = ei[NE + e];
    float norm = g_deg[s] * ew[e] * g_deg[d];   // g_deg holds dinv now
    int pos = atomicAdd(&g_woff[d], 1);
    g_csrc[pos] = s;
    g_cnorm[pos] = norm;
}

// K5: layer-1 CSR aggregation. 9 threads per node (float4 chunks), no atomics.
// Includes self-loop: dinv^2 * x[n].
__global__ void k_agg1(int total) {
    int t = blockIdx.x * blockDim.x + threadIdx.x;
    if (t >= total) return;
    int n = t / 9;
    int q = t - n * 9;
    float di = g_deg[n];
    const float4* xp = (const float4*)g_xpad;
    float4 acc = xp[n * 9 + q];
    float d2 = di * di;
    acc.x *= d2; acc.y *= d2; acc.z *= d2; acc.w *= d2;
    int e = g_off[n], end = g_off[n + 1];
    for (; e < end; e++) {
        int s = g_csrc[e];
        float w = g_cnorm[e];
        float4 v = xp[s * 9 + q];
        acc.x += w * v.x; acc.y += w * v.y; acc.z += w * v.z; acc.w += w * v.w;
    }
    ((float4*)g_aggx)[n * 9 + q] = acc;
}

// K6: h1 = relu(aggx @ W1 + b1). 256 threads = 4 nodes x 64 outputs
__global__ void k_gemm1(const float* __restrict__ W1, const float* __restrict__ b1) {
    __shared__ float sW[F0 * F1];
    __shared__ float sb[F1];
    __shared__ float sx[4 * F0P];
    int tid = threadIdx.x;
    for (int i = tid; i < F0 * F1; i += 256) sW[i] = W1[i];
    if (tid < F1) sb[tid] = b1[tid];
    int base = blockIdx.x * 4;
    for (int i = tid; i < 4 * F0P; i += 256) {
        int n = base + i / F0P;
        sx[i] = (n < NN) ? g_aggx[n * F0P + (i % F0P)] : 0.0f;
    }
    __syncthreads();
    int o  = tid & 63;
    int ni = tid >> 6;
    int n = base + ni;
    if (n >= NN) return;
    float acc = sb[o];
#pragma unroll
    for (int f = 0; f < F0; f++)
        acc += sx[ni * F0P + f] * sW[f * F1 + o];
    g_h1[n * F1 + o] = fmaxf(acc, 0.0f);
}

// K7: h2 = h1 @ W2
__global__ void k_h2(const float* __restrict__ W2) {
    __shared__ float sW[F1 * 2];
    if (threadIdx.x < F1 * 2) sW[threadIdx.x] = W2[threadIdx.x];
    __syncthreads();
    int n = blockIdx.x * blockDim.x + threadIdx.x;
    if (n >= NN) return;
    const float4* hv = (const float4*)(g_h1 + n * F1);
    float a0 = 0.0f, a1 = 0.0f;
#pragma unroll
    for (int i = 0; i < 16; i++) {
        float4 v = hv[i];
        int k = i * 4;
        a0 += v.x * sW[(k + 0) * 2 + 0] + v.y * sW[(k + 1) * 2 + 0]
            + v.z * sW[(k + 2) * 2 + 0] + v.w * sW[(k + 3) * 2 + 0];
        a1 += v.x * sW[(k + 0) * 2 + 1] + v.y * sW[(k + 1) * 2 + 1]
            + v.z * sW[(k + 2) * 2 + 1] + v.w * sW[(k + 3) * 2 + 1];
    }
    ((float2*)g_h2)[n] = make_float2(a0, a1);
}

// K8: layer-2 CSR aggregation. 1 thread per node, no atomics, self-loop fused.
__global__ void k_agg2() {
    int n = blockIdx.x * blockDim.x + threadIdx.x;
    if (n >= NN) return;
    float di = g_deg[n];
    float2 h = ((const float2*)g_h2)[n];
    float d2 = di * di;
    float a0 = d2 * h.x, a1 = d2 * h.y;
    int e = g_off[n], end = g_off[n + 1];
    const float2* h2v = (const float2*)g_h2;
    for (; e < end; e++) {
        int s = g_csrc[e];
        float w = g_cnorm[e];
        float2 v = h2v[s];
        a0 += w * v.x;
        a1 += w * v.y;
    }
    ((float2*)g_agg2)[n] = make_float2(a0, a1);
}

// K9: +b2, log_softmax over 2 classes
__global__ void k_out(const float* __restrict__ b2, float* __restrict__ out) {
    int n = blockIdx.x * blockDim.x + threadIdx.x;
    if (n >= NN) return;
    float2 a = ((const float2*)g_agg2)[n];
    a.x += b2[0];
    a.y += b2[1];
    float m = fmaxf(a.x, a.y);
    float lse = m + logf(expf(a.x - m) + expf(a.y - m));
    ((float2*)out)[n] = make_float2(a.x - lse, a.y - lse);
}

extern "C" void kernel_launch(void* const* d_in, const int* in_sizes, int n_in,
                              void* d_out, int out_size) {
    const float* x = nullptr;
    const int* ei = nullptr;
    const float* ew = nullptr;
    const float *W1 = nullptr, *b1 = nullptr, *W2 = nullptr, *b2 = nullptr;
    for (int i = 0; i < n_in; i++) {
        switch (in_sizes[i]) {
            case NN * F0:  x  = (const float*)d_in[i]; break;
            case 2 * NE:   ei = (const int*)d_in[i]; break;
            case NE:       ew = (const float*)d_in[i]; break;
            case F0 * F1:  W1 = (const float*)d_in[i]; break;
            case F1:       b1 = (const float*)d_in[i]; break;
            case F1 * 2:   W2 = (const float*)d_in[i]; break;
            case 2:        b2 = (const float*)d_in[i]; break;
            default: break;
        }
    }
    float* out = (float*)d_out;

    const int B = 256;
    k_init<<<(NN * F0P + B - 1) / B, B>>>(x);
    k_hist<<<(NE + B - 1) / B, B>>>(ei, ew);
    k_dinv<<<(NN + B - 1) / B, B>>>();
    k_scan<<<1, 1024>>>();
    k_scatter<<<(NE + B - 1) / B, B>>>(ei, ew);
    int tot1 = NN * 9;
    k_agg1<<<(tot1 + B - 1) / B, B>>>(tot1);
    k_gemm1<<<(NN + 3) / 4, 256>>>(W1, b1);
    k_h2<<<(NN + B - 1) / B, B>>>(W2);
    k_agg2<<<(NN + B - 1) / B, B>>>();
    k_out<<<(NN + B - 1) / B, B>>>(b2, out);
}

// round 6
// speedup vs baseline: 1.6935x; 1.5726x over previous
#include <cuda_runtime.h>
#include <math.h>

#define NN 100000
#define NE 3200000
#define F0 35
#define F0P 36
#define F1 64
#define SCAN_B 1024
#define NBLK ((NN + SCAN_B - 1) / SCAN_B)   // 98

// ---- scratch (device globals) ----
__device__ float g_deg[NN];                        // weighted deg, then dinv
__device__ int   g_cnt[NN];                        // in-degree count
__device__ int   g_off[NN + 1];                    // CSR offsets
__device__ int   g_woff[NN];                       // working offsets for scatter
__device__ int   g_bsum[128];                      // per-block sums
__device__ int   g_boff[128];                      // per-block exclusive offsets
__device__ int   g_csrc[NE];                       // CSR: src per edge (dst-sorted)
__device__ float g_cnorm[NE];                      // CSR: norm per edge
__device__ __align__(16) float g_xpad[NN * F0P];   // x padded to 36 cols
__device__ __align__(16) float g_aggx[NN * F0P];   // layer-1 aggregate
__device__ __align__(16) float g_h1[NN * F1];      // relu(aggx@W1+b1)
__device__ __align__(8)  float g_h2[NN * 2];       // h1@W2
__device__ __align__(8)  float g_agg2[NN * 2];     // layer-2 aggregate

// K0: pad x, init deg=1 (self-loop weight), cnt=0
__global__ void k_init(const float* __restrict__ x) {
    int idx = blockIdx.x * blockDim.x + threadIdx.x;
    if (idx >= NN * F0P) return;
    int n = idx / F0P;
    int f = idx - n * F0P;
    g_xpad[idx] = (f < F0) ? x[n * F0 + f] : 0.0f;
    if (f == 0) { g_deg[n] = 1.0f; g_cnt[n] = 0; }
}

// K1: weighted in-degree + count histogram
__global__ void k_hist(const int* __restrict__ ei, const float* __restrict__ ew) {
    int e = blockIdx.x * blockDim.x + threadIdx.x;
    if (e >= NE) return;
    int d = ei[NE + e];
    atomicAdd(&g_deg[d], ew[e]);
    atomicAdd(&g_cnt[d], 1);
}

// K2: deg -> dinv
__global__ void k_dinv() {
    int n = blockIdx.x * blockDim.x + threadIdx.x;
    if (n >= NN) return;
    float d = g_deg[n];
    g_deg[n] = (d > 0.0f) ? rsqrtf(d) : 0.0f;
}

// K3a: per-block sums of g_cnt
__global__ void k_scan1() {
    __shared__ int s[SCAN_B];
    int n = blockIdx.x * SCAN_B + threadIdx.x;
    s[threadIdx.x] = (n < NN) ? g_cnt[n] : 0;
    __syncthreads();
    for (int o = SCAN_B / 2; o > 0; o >>= 1) {
        if (threadIdx.x < o) s[threadIdx.x] += s[threadIdx.x + o];
        __syncthreads();
    }
    if (threadIdx.x == 0) g_bsum[blockIdx.x] = s[0];
}

// K3b: single-block scan of block sums (NBLK <= 128)
__global__ void k_scan2() {
    __shared__ int s[128];
    int t = threadIdx.x;
    int v = (t < NBLK) ? g_bsum[t] : 0;
    s[t] = v;
    __syncthreads();
    for (int o = 1; o < 128; o <<= 1) {
        int u = (t >= o) ? s[t - o] : 0;
        __syncthreads();
        s[t] += u;
        __syncthreads();
    }
    g_boff[t] = s[t] - v;                 // exclusive prefix
    if (t == NBLK - 1) g_off[NN] = s[t];  // total
}

// K3c: block-local scan + block offset -> g_off / g_woff
__global__ void k_scan3() {
    __shared__ int s[SCAN_B];
    int n = blockIdx.x * SCAN_B + threadIdx.x;
    int v = (n < NN) ? g_cnt[n] : 0;
    s[threadIdx.x] = v;
    __syncthreads();
    for (int o = 1; o < SCAN_B; o <<= 1) {
        int u = (threadIdx.x >= o) ? s[threadIdx.x - o] : 0;
        __syncthreads();
        s[threadIdx.x] += u;
        __syncthreads();
    }
    if (n < NN) {
        int excl = s[threadIdx.x] - v + g_boff[blockIdx.x];
        g_off[n] = excl;
        g_woff[n] = excl;
    }
}

// K4: scatter edges into CSR (dst-sorted), computing norm on the fly
__global__ void k_scatter(const int* __restrict__ ei, const float* __restrict__ ew) {
    int e = blockIdx.x * blockDim.x + threadIdx.x;
    if (e >= NE) return;
    int s = ei[e];
    int d = ei[NE + e];
    float norm = g_deg[s] * ew[e] * g_deg[d];   // g_deg holds dinv now
    int pos = atomicAdd(&g_woff[d], 1);
    g_csrc[pos] = s;
    g_cnorm[pos] = norm;
}

// K5: layer-1 CSR aggregation. 9 threads per node (float4 chunks), no atomics.
__global__ void k_agg1(int total) {
    int t = blockIdx.x * blockDim.x + threadIdx.x;
    if (t >= total) return;
    int n = t / 9;
    int q = t - n * 9;
    float di = g_deg[n];
    const float4* xp = (const float4*)g_xpad;
    float4 acc = xp[n * 9 + q];
    float d2 = di * di;
    acc.x *= d2; acc.y *= d2; acc.z *= d2; acc.w *= d2;
    int e = g_off[n], end = g_off[n + 1];
    for (; e < end; e++) {
        int s = g_csrc[e];
        float w = g_cnorm[e];
        float4 v = xp[s * 9 + q];
        acc.x += w * v.x; acc.y += w * v.y; acc.z += w * v.z; acc.w += w * v.w;
    }
    ((float4*)g_aggx)[n * 9 + q] = acc;
}

// K6: h1 = relu(aggx @ W1 + b1). 256 threads = 4 nodes x 64 outputs
__global__ void k_gemm1(const float* __restrict__ W1, const float* __restrict__ b1) {
    __shared__ float sW[F0 * F1];
    __shared__ float sb[F1];
    __shared__ float sx[4 * F0P];
    int tid = threadIdx.x;
    for (int i = tid; i < F0 * F1; i += 256) sW[i] = W1[i];
    if (tid < F1) sb[tid] = b1[tid];
    int base = blockIdx.x * 4;
    for (int i = tid; i < 4 * F0P; i += 256) {
        int n = base + i / F0P;
        sx[i] = (n < NN) ? g_aggx[n * F0P + (i % F0P)] : 0.0f;
    }
    __syncthreads();
    int o  = tid & 63;
    int ni = tid >> 6;
    int n = base + ni;
    if (n >= NN) return;
    float acc = sb[o];
#pragma unroll
    for (int f = 0; f < F0; f++)
        acc += sx[ni * F0P + f] * sW[f * F1 + o];
    g_h1[n * F1 + o] = fmaxf(acc, 0.0f);
}

// K7: h2 = h1 @ W2
__global__ void k_h2(const float* __restrict__ W2) {
    __shared__ float sW[F1 * 2];
    if (threadIdx.x < F1 * 2) sW[threadIdx.x] = W2[threadIdx.x];
    __syncthreads();
    int n = blockIdx.x * blockDim.x + threadIdx.x;
    if (n >= NN) return;
    const float4* hv = (const float4*)(g_h1 + n * F1);
    float a0 = 0.0f, a1 = 0.0f;
#pragma unroll
    for (int i = 0; i < 16; i++) {
        float4 v = hv[i];
        int k = i * 4;
        a0 += v.x * sW[(k + 0) * 2 + 0] + v.y * sW[(k + 1) * 2 + 0]
            + v.z * sW[(k + 2) * 2 + 0] + v.w * sW[(k + 3) * 2 + 0];
        a1 += v.x * sW[(k + 0) * 2 + 1] + v.y * sW[(k + 1) * 2 + 1]
            + v.z * sW[(k + 2) * 2 + 1] + v.w * sW[(k + 3) * 2 + 1];
    }
    ((float2*)g_h2)[n] = make_float2(a0, a1);
}

// K8: layer-2 CSR aggregation. 1 thread per node, no atomics.
__global__ void k_agg2() {
    int n = blockIdx.x * blockDim.x + threadIdx.x;
    if (n >= NN) return;
    float di = g_deg[n];
    float2 h = ((const float2*)g_h2)[n];
    float d2 = di * di;
    float a0 = d2 * h.x, a1 = d2 * h.y;
    int e = g_off[n], end = g_off[n + 1];
    const float2* h2v = (const float2*)g_h2;
    for (; e < end; e++) {
        int s = g_csrc[e];
        float w = g_cnorm[e];
        float2 v = h2v[s];
        a0 += w * v.x;
        a1 += w * v.y;
    }
    ((float2*)g_agg2)[n] = make_float2(a0, a1);
}

// K9: +b2, log_softmax over 2 classes
__global__ void k_out(const float* __restrict__ b2, float* __restrict__ out) {
    int n = blockIdx.x * blockDim.x + threadIdx.x;
    if (n >= NN) return;
    float2 a = ((const float2*)g_agg2)[n];
    a.x += b2[0];
    a.y += b2[1];
    float m = fmaxf(a.x, a.y);
    float lse = m + logf(expf(a.x - m) + expf(a.y - m));
    ((float2*)out)[n] = make_float2(a.x - lse, a.y - lse);
}

extern "C" void kernel_launch(void* const* d_in, const int* in_sizes, int n_in,
                              void* d_out, int out_size) {
    const float* x = nullptr;
    const int* ei = nullptr;
    const float* ew = nullptr;
    const float *W1 = nullptr, *b1 = nullptr, *W2 = nullptr, *b2 = nullptr;
    for (int i = 0; i < n_in; i++) {
        switch (in_sizes[i]) {
            case NN * F0:  x  = (const float*)d_in[i]; break;
            case 2 * NE:   ei = (const int*)d_in[i]; break;
            case NE:       ew = (const float*)d_in[i]; break;
            case F0 * F1:  W1 = (const float*)d_in[i]; break;
            case F1:       b1 = (const float*)d_in[i]; break;
            case F1 * 2:   W2 = (const float*)d_in[i]; break;
            case 2:        b2 = (const float*)d_in[i]; break;
            default: break;
        }
    }
    float* out = (float*)d_out;

    const int B = 256;
    k_init<<<(NN * F0P + B - 1) / B, B>>>(x);
    k_hist<<<(NE + B - 1) / B, B>>>(ei, ew);
    k_dinv<<<(NN + B - 1) / B, B>>>();
    k_scan1<<<NBLK, SCAN_B>>>();
    k_scan2<<<1, 128>>>();
    k_scan3<<<NBLK, SCAN_B>>>();
    k_scatter<<<(NE + B - 1) / B, B>>>(ei, ew);
    int tot1 = NN * 9;
    k_agg1<<<(tot1 + B - 1) / B, B>>>(tot1);
    k_gemm1<<<(NN + 3) / 4, 256>>>(W1, b1);
    k_h2<<<(NN + B - 1) / B, B>>>(W2);
    k_agg2<<<(NN + B - 1) / B, B>>>();
    k_out<<<(NN + B - 1) / B, B>>>(b2, out);
}

// round 7
// speedup vs baseline: 1.9714x; 1.1641x over previous
#include <cuda_runtime.h>
#include <math.h>

#define NN 100000
#define NE 3200000
#define F0 35
#define F0P 36
#define F1 64
#define SCAN_B 1024
#define NBLK ((NN + SCAN_B - 1) / SCAN_B)   // 98

// ---- scratch (device globals) ----
__device__ float g_dinv[NN];                       // 1/sqrt(weighted deg)
__device__ int   g_cnt[NN];                        // in-degree count
__device__ int   g_off[NN + 1];                    // CSR offsets
__device__ int   g_woff[NN];                       // working offsets for scatter
__device__ int   g_bsum[128];                      // per-block sums
__device__ int   g_boff[128];                      // per-block exclusive offsets
__device__ __align__(8) int2 g_edge[NE];           // CSR: (src, ew-bits) dst-sorted
__device__ __align__(16) float g_xpad[NN * F0P];   // x padded to 36 cols
__device__ __align__(16) float g_y[NN * F0P];      // dinv[n] * x[n]
__device__ __align__(16) float g_aggx[NN * F0P];   // layer-1 aggregate
__device__ __align__(16) float g_h1[NN * F1];      // relu(aggx@W1+b1)
__device__ __align__(8)  float g_h2s[NN * 2];      // dinv[n] * (h1@W2)

// K0: pad x, zero counts
__global__ void k_init(const float* __restrict__ x) {
    int idx = blockIdx.x * blockDim.x + threadIdx.x;
    if (idx >= NN * F0P) return;
    int n = idx / F0P;
    int f = idx - n * F0P;
    g_xpad[idx] = (f < F0) ? x[n * F0 + f] : 0.0f;
    if (f == 0) g_cnt[n] = 0;
}

// K1: in-degree count histogram (int atomics only)
__global__ void k_hist(const int* __restrict__ ei) {
    int e = blockIdx.x * blockDim.x + threadIdx.x;
    if (e >= NE) return;
    atomicAdd(&g_cnt[ei[NE + e]], 1);
}

// K2a: per-block sums of g_cnt
__global__ void k_scan1() {
    __shared__ int s[SCAN_B];
    int n = blockIdx.x * SCAN_B + threadIdx.x;
    s[threadIdx.x] = (n < NN) ? g_cnt[n] : 0;
    __syncthreads();
    for (int o = SCAN_B / 2; o > 0; o >>= 1) {
        if (threadIdx.x < o) s[threadIdx.x] += s[threadIdx.x + o];
        __syncthreads();
    }
    if (threadIdx.x == 0) g_bsum[blockIdx.x] = s[0];
}

// K2b: single-block scan of block sums
__global__ void k_scan2() {
    __shared__ int s[128];
    int t = threadIdx.x;
    int v = (t < NBLK) ? g_bsum[t] : 0;
    s[t] = v;
    __syncthreads();
    for (int o = 1; o < 128; o <<= 1) {
        int u = (t >= o) ? s[t - o] : 0;
        __syncthreads();
        s[t] += u;
        __syncthreads();
    }
    g_boff[t] = s[t] - v;
    if (t == NBLK - 1) g_off[NN] = s[t];
}

// K2c: block-local scan + block offset
__global__ void k_scan3() {
    __shared__ int s[SCAN_B];
    int n = blockIdx.x * SCAN_B + threadIdx.x;
    int v = (n < NN) ? g_cnt[n] : 0;
    s[threadIdx.x] = v;
    __syncthreads();
    for (int o = 1; o < SCAN_B; o <<= 1) {
        int u = (threadIdx.x >= o) ? s[threadIdx.x - o] : 0;
        __syncthreads();
        s[threadIdx.x] += u;
        __syncthreads();
    }
    if (n < NN) {
        int excl = s[threadIdx.x] - v + g_boff[blockIdx.x];
        g_off[n] = excl;
        g_woff[n] = excl;
    }
}

// K3: scatter edges into CSR: one packed int2 {src, ew bits} per edge
__global__ void k_scatter(const int* __restrict__ ei, const float* __restrict__ ew) {
    int e = blockIdx.x * blockDim.x + threadIdx.x;
    if (e >= NE) return;
    int s = ei[e];
    int d = ei[NE + e];
    int pos = atomicAdd(&g_woff[d], 1);
    g_edge[pos] = make_int2(s, __float_as_int(ew[e]));
}

// K4: weighted degree via coalesced segment sum; dinv = rsqrt(1 + sum)
__global__ void k_deg() {
    int n = blockIdx.x * blockDim.x + threadIdx.x;
    if (n >= NN) return;
    int e = g_off[n], end = g_off[n + 1];
    float s = 1.0f;                           // self-loop weight
    for (; e < end; e++) s += __int_as_float(g_edge[e].y);
    g_dinv[n] = rsqrtf(s);
}

// K5: y = dinv[n] * xpad[n]
__global__ void k_scale() {
    int i = blockIdx.x * blockDim.x + threadIdx.x;
    if (i >= NN * 9) return;
    int n = i / 9;
    float di = g_dinv[n];
    float4 v = ((const float4*)g_xpad)[i];
    ((float4*)g_y)[i] = make_float4(di * v.x, di * v.y, di * v.z, di * v.w);
}

// K6: layer-1 CSR aggregation: aggx[n] = dinv[n]*(y[n] + sum_e ew*y[src])
__global__ void k_agg1() {
    int t = blockIdx.x * blockDim.x + threadIdx.x;
    if (t >= NN * 9) return;
    int n = t / 9;
    int q = t - n * 9;
    float di = g_dinv[n];
    const float4* yp = (const float4*)g_y;
    float4 acc = yp[n * 9 + q];               // self-loop (y[n] = dinv*x[n])
    int e = g_off[n], end = g_off[n + 1];
    for (; e < end; e++) {
        int2 ed = g_edge[e];
        float w = __int_as_float(ed.y);
        float4 v = yp[ed.x * 9 + q];
        acc.x += w * v.x; acc.y += w * v.y; acc.z += w * v.z; acc.w += w * v.w;
    }
    ((float4*)g_aggx)[n * 9 + q] = make_float4(di * acc.x, di * acc.y, di * acc.z, di * acc.w);
}

// K7: h1 = relu(aggx @ W1 + b1). 32 nodes/block, 8 threads/node x 8 outputs
__global__ void k_gemm1(const float* __restrict__ W1, const float* __restrict__ b1) {
    __shared__ float sW[F0 * F1];
    __shared__ float sb[F1];
    __shared__ float sx[32 * F0P];
    int tid = threadIdx.x;
    for (int i = tid; i < F0 * F1; i += 256) sW[i] = W1[i];
    if (tid < F1) sb[tid] = b1[tid];
    int base = blockIdx.x * 32;
    const float4* ax = (const float4*)g_aggx;
    for (int i = tid; i < 32 * 9; i += 256) {
        int n = base + i / 9;
        ((float4*)sx)[i] = (n < NN) ? ax[n * 9 + (i % 9)]
                                    : make_float4(0.f, 0.f, 0.f, 0.f);
    }
    __syncthreads();
    int ni = tid >> 3;
    int o0 = (tid & 7) * 8;
    int n = base + ni;
    if (n >= NN) return;
    float acc[8];
#pragma unroll
    for (int j = 0; j < 8; j++) acc[j] = sb[o0 + j];
    const float* xr = sx + ni * F0P;
#pragma unroll
    for (int f = 0; f < F0; f++) {
        float xv = xr[f];
        const float* wr = sW + f * F1 + o0;
#pragma unroll
        for (int j = 0; j < 8; j++) acc[j] += xv * wr[j];
    }
    float* o = g_h1 + n * F1 + o0;
#pragma unroll
    for (int j = 0; j < 8; j++) o[j] = fmaxf(acc[j], 0.0f);
}

// K8: h2s = dinv[n] * (h1 @ W2)
__global__ void k_h2(const float* __restrict__ W2) {
    __shared__ float sW[F1 * 2];
    if (threadIdx.x < F1 * 2) sW[threadIdx.x] = W2[threadIdx.x];
    __syncthreads();
    int n = blockIdx.x * blockDim.x + threadIdx.x;
    if (n >= NN) return;
    const float4* hv = (const float4*)(g_h1 + n * F1);
    float a0 = 0.0f, a1 = 0.0f;
#pragma unroll
    for (int i = 0; i < 16; i++) {
        float4 v = hv[i];
        int k = i * 4;
        a0 += v.x * sW[(k + 0) * 2 + 0] + v.y * sW[(k + 1) * 2 + 0]
            + v.z * sW[(k + 2) * 2 + 0] + v.w * sW[(k + 3) * 2 + 0];
        a1 += v.x * sW[(k + 0) * 2 + 1] + v.y * sW[(k + 1) * 2 + 1]
            + v.z * sW[(k + 2) * 2 + 1] + v.w * sW[(k + 3) * 2 + 1];
    }
    float di = g_dinv[n];
    ((float2*)g_h2s)[n] = make_float2(di * a0, di * a1);
}

// K9: layer-2 aggregation + bias + log_softmax, fused
__global__ void k_agg2out(const float* __restrict__ b2, float* __restrict__ out) {
    int n = blockIdx.x * blockDim.x + threadIdx.x;
    if (n >= NN) return;
    float di = g_dinv[n];
    const float2* hs = (const float2*)g_h2s;
    float2 h = hs[n];                         // self-loop (h2s[n] = dinv*h2[n])
    float a0 = h.x, a1 = h.y;
    int e = g_off[n], end = g_off[n + 1];
    for (; e < end; e++) {
        int2 ed = g_edge[e];
        float w = __int_as_float(ed.y);
        float2 v = hs[ed.x];
        a0 += w * v.x;
        a1 += w * v.y;
    }
    a0 = di * a0 + b2[0];
    a1 = di * a1 + b2[1];
    float m = fmaxf(a0, a1);
    float lse = m + logf(expf(a0 - m) + expf(a1 - m));
    ((float2*)out)[n] = make_float2(a0 - lse, a1 - lse);
}

extern "C" void kernel_launch(void* const* d_in, const int* in_sizes, int n_in,
                              void* d_out, int out_size) {
    const float* x = nullptr;
    const int* ei = nullptr;
    const float* ew = nullptr;
    const float *W1 = nullptr, *b1 = nullptr, *W2 = nullptr, *b2 = nullptr;
    for (int i = 0; i < n_in; i++) {
        switch (in_sizes[i]) {
            case NN * F0:  x  = (const float*)d_in[i]; break;
            case 2 * NE:   ei = (const int*)d_in[i]; break;
            case NE:       ew = (const float*)d_in[i]; break;
            case F0 * F1:  W1 = (const float*)d_in[i]; break;
            case F1:       b1 = (const float*)d_in[i]; break;
            case F1 * 2:   W2 = (const float*)d_in[i]; break;
            case 2:        b2 = (const float*)d_in[i]; break;
            default: break;
        }
    }
    float* out = (float*)d_out;

    const int B = 256;
    k_init<<<(NN * F0P + B - 1) / B, B>>>(x);
    k_hist<<<(NE + B - 1) / B, B>>>(ei);
    k_scan1<<<NBLK, SCAN_B>>>();
    k_scan2<<<1, 128>>>();
    k_scan3<<<NBLK, SCAN_B>>>();
    k_scatter<<<(NE + B - 1) / B, B>>>(ei, ew);
    k_deg<<<(NN + B - 1) / B, B>>>();
    k_scale<<<(NN * 9 + B - 1) / B, B>>>();
    k_agg1<<<(NN * 9 + B - 1) / B, B>>>();
    k_gemm1<<<(NN + 31) / 32, 256>>>(W1, b1);
    k_h2<<<(NN + B - 1) / B, B>>>(W2);
    k_agg2out<<<(NN + B - 1) / B, B>>>(b2, out);
}